// round 11
// baseline (speedup 1.0000x reference)
#include <cuda_runtime.h>
#include <math.h>

// CharRNN, round 11: two-kernel split.
// Kernel A: recurrence only (256 CTAs x 128 thr, 2 rows/CTA, 2 CTAs/SM,
//   W_hh column register-resident, one __syncthreads/step, h streamed to
//   global scratch). Lean registers -> no spills.
// Kernel B: bulk logits GEMM from scratch (4096 CTAs x 128 thr, warp = 32
//   timesteps of one row, lane = vocab column, W_hy column in registers).

#define ULL unsigned long long

__device__ float hsc[67108864];   // [512 rows][1024 t][128 j]

__device__ __forceinline__ ULL ffma2(ULL a, ULL b, ULL c) {
    ULL d;
    asm("fma.rn.f32x2 %0, %1, %2, %3;" : "=l"(d) : "l"(a), "l"(b), "l"(c));
    return d;
}
__device__ __forceinline__ ULL pack2(float lo, float hi) {
    ULL d;
    asm("mov.b64 %0, {%1, %2};" : "=l"(d) : "f"(lo), "f"(hi));
    return d;
}
__device__ __forceinline__ float sum2(ULL a) {
    float lo, hi;
    asm("mov.b64 {%0, %1}, %2;" : "=f"(lo), "=f"(hi) : "l"(a));
    return lo + hi;
}
__device__ __forceinline__ float fast_tanh(float x) {
    return 1.0f - __fdividef(2.0f, __expf(2.0f * x) + 1.0f);
}

// ================= Kernel A: recurrence =================
__global__ void __launch_bounds__(128, 2) rnn_recur_kernel(
    const int*   __restrict__ x,      // [512][1024]
    const float* __restrict__ emb,    // [32][32]
    const float* __restrict__ Wxh,    // [32][128]
    const float* __restrict__ Whh,    // [128][128]
    const float* __restrict__ bh,     // [128]
    float*       __restrict__ out)    // final hidden at out+16777216
{
    __shared__ __align__(16) float table[32 * 128];   // xh lookup
    __shared__ __align__(16) float hbuf[2][2 * 128];
    __shared__ int xs[2 * 128];

    const int tid = threadIdx.x;      // 0..127
    const int j   = tid;
    const int r0  = blockIdx.x * 2;

    for (int c = 0; c < 32; c++) {
        float s = bh[j];
        #pragma unroll 8
        for (int e = 0; e < 32; e++)
            s = fmaf(emb[c * 32 + e], Wxh[e * 128 + j], s);
        table[c * 128 + j] = s;
    }
    hbuf[1][j] = 0.f; hbuf[1][128 + j] = 0.f;   // h_{-1}=0, parity 1

    ULL Wb[64];
    #pragma unroll
    for (int k = 0; k < 64; k++)
        Wb[k] = pack2(Whh[(2 * k) * 128 + j], Whh[(2 * k + 1) * 128 + j]);

    float* scr0 = hsc + (size_t)r0 * 131072;
    float* scr1 = scr0 + 131072;

    for (int t = 0; t < 1024; t++) {
        __syncthreads();                  // h(t-1) visible
        const int tloc = t & 127;
        if (tloc == 0) {
            xs[tid]       = x[r0 * 1024 + t + tid];
            xs[128 + tid] = x[(r0 + 1) * 1024 + t + tid];
            __syncthreads();
        }
        const int br = (t + 1) & 1;
        const int bw = t & 1;

        const ulonglong2* h0 = (const ulonglong2*)(hbuf[br]);
        const ulonglong2* h1 = (const ulonglong2*)(hbuf[br] + 128);
        const int c0 = xs[tloc];
        const int c1 = xs[128 + tloc];
        // 8 accumulator chains (4 per row), 16 deep each
        ULL a0 = pack2(table[c0 * 128 + j], 0.0f), a1 = 0ull, a2 = 0ull, a3 = 0ull;
        ULL b0 = pack2(table[c1 * 128 + j], 0.0f), b1 = 0ull, b2 = 0ull, b3 = 0ull;
        #pragma unroll
        for (int k = 0; k < 16; k++) {
            ulonglong2 ha = h0[2 * k];
            ulonglong2 hb = h0[2 * k + 1];
            ulonglong2 hc = h1[2 * k];
            ulonglong2 hd = h1[2 * k + 1];
            a0 = ffma2(ha.x, Wb[4 * k],     a0);
            b0 = ffma2(hc.x, Wb[4 * k],     b0);
            a1 = ffma2(ha.y, Wb[4 * k + 1], a1);
            b1 = ffma2(hc.y, Wb[4 * k + 1], b1);
            a2 = ffma2(hb.x, Wb[4 * k + 2], a2);
            b2 = ffma2(hd.x, Wb[4 * k + 2], b2);
            a3 = ffma2(hb.y, Wb[4 * k + 3], a3);
            b3 = ffma2(hd.y, Wb[4 * k + 3], b3);
        }
        float na = fast_tanh((sum2(a0) + sum2(a1)) + (sum2(a2) + sum2(a3)));
        float nb = fast_tanh((sum2(b0) + sum2(b1)) + (sum2(b2) + sum2(b3)));
        hbuf[bw][j]       = na;
        hbuf[bw][128 + j] = nb;
        scr0[t * 128 + j] = na;
        scr1[t * 128 + j] = nb;
    }

    out[16777216u + (size_t)r0 * 128 + j]       = hbuf[1][j];
    out[16777216u + (size_t)(r0 + 1) * 128 + j] = hbuf[1][128 + j];
}

// ================= Kernel B: bulk logits =================
// blockIdx.x = r * 8 + tb  (row r, t-block tb of 128 steps)
// warp w covers t in [tb*128 + 32w, +32); lane v: logits[r][t][v].
__global__ void __launch_bounds__(128, 3) rnn_logits_kernel(
    const float* __restrict__ Why,    // [128][32]
    const float* __restrict__ by_g,   // [32]
    float*       __restrict__ out)    // logits [512][1024][32]
{
    const int tid = threadIdx.x;
    const int v   = tid & 31;
    const int w   = tid >> 5;
    const int r   = blockIdx.x >> 3;
    const int tb  = blockIdx.x & 7;

    ULL Wy[64];
    #pragma unroll
    for (int k = 0; k < 64; k++)
        Wy[k] = pack2(Why[(2 * k) * 32 + v], Why[(2 * k + 1) * 32 + v]);
    const float byv = by_g[v];

    const int t0 = tb * 128 + w * 32;
    const float* hrow = hsc + (size_t)r * 131072;
    float* orow = out + ((size_t)r * 1024 + t0) * 32 + v;

    for (int tt = 0; tt < 32; tt++) {
        const ulonglong2* hp = (const ulonglong2*)(hrow + (t0 + tt) * 128);
        ULL s0 = 0ull, s1 = 0ull, s2 = 0ull, s3 = 0ull;
        #pragma unroll
        for (int k = 0; k < 16; k++) {
            ulonglong2 ha = hp[2 * k];
            ulonglong2 hb = hp[2 * k + 1];
            s0 = ffma2(ha.x, Wy[4 * k],     s0);
            s1 = ffma2(ha.y, Wy[4 * k + 1], s1);
            s2 = ffma2(hb.x, Wy[4 * k + 2], s2);
            s3 = ffma2(hb.y, Wy[4 * k + 3], s3);
        }
        orow[tt * 32] = (sum2(s0) + sum2(s1)) + (sum2(s2) + sum2(s3)) + byv;
    }
}

extern "C" void kernel_launch(void* const* d_in, const int* in_sizes, int n_in,
                              void* d_out, int out_size) {
    (void)in_sizes; (void)n_in; (void)out_size;
    const int*   x   = (const int*)d_in[0];
    const float* emb = (const float*)d_in[1];
    const float* Wxh = (const float*)d_in[2];
    const float* Whh = (const float*)d_in[3];
    const float* bh  = (const float*)d_in[4];
    const float* Why = (const float*)d_in[5];
    const float* by  = (const float*)d_in[6];
    float* out = (float*)d_out;

    rnn_recur_kernel<<<256, 128>>>(x, emb, Wxh, Whh, bh, out);
    rnn_logits_kernel<<<4096, 128>>>(Why, by, out);
}

// round 12
// speedup vs baseline: 1.6228x; 1.6228x over previous
#include <cuda_runtime.h>
#include <math.h>

// CharRNN, round 12: fused recurrence + bulk-logits tail, lean registers.
// Phase 1: 256 CTAs x 128 thr, 2 rows/CTA, 2 CTAs/SM. W_hh column j in 64
//   f32x2 regs, one __syncthreads/step, h(t) streamed to global scratch.
// Phase 2 (same CTA, ~40 regs): logits for own 2 rows. W_hy in smem
//   (broadcast LDS), h staged in 32-t smem tiles (coalesced LDG, stride-132
//   padding), lane = timestep, warp = 8 vocab columns.

#define ULL unsigned long long

__device__ float hsc[67108864];   // [512 rows][1024 t][128 j]

__device__ __forceinline__ ULL ffma2(ULL a, ULL b, ULL c) {
    ULL d;
    asm("fma.rn.f32x2 %0, %1, %2, %3;" : "=l"(d) : "l"(a), "l"(b), "l"(c));
    return d;
}
__device__ __forceinline__ ULL pack2(float lo, float hi) {
    ULL d;
    asm("mov.b64 %0, {%1, %2};" : "=l"(d) : "f"(lo), "f"(hi));
    return d;
}
__device__ __forceinline__ float sum2(ULL a) {
    float lo, hi;
    asm("mov.b64 {%0, %1}, %2;" : "=f"(lo), "=f"(hi) : "l"(a));
    return lo + hi;
}
__device__ __forceinline__ float fast_tanh(float x) {
    return 1.0f - __fdividef(2.0f, __expf(2.0f * x) + 1.0f);
}

// pool layout (floats):
//  phase 1: table[0..4096) | hbuf[4096..4608) | xs(int)[4608..4864)
//  phase 2: hs[0..4224) (32 t x 132 stride) | Wp ULL[2048] at [4352..8448)
__global__ void __launch_bounds__(128, 2) charrnn_kernel(
    const int*   __restrict__ x,      // [512][1024]
    const float* __restrict__ emb,    // [32][32]
    const float* __restrict__ Wxh,    // [32][128]
    const float* __restrict__ Whh,    // [128][128]
    const float* __restrict__ bh,     // [128]
    const float* __restrict__ Why,    // [128][32]
    const float* __restrict__ by_g,   // [32]
    float*       __restrict__ out)    // logits [512][1024][32] ++ hidden [512][128]
{
    __shared__ __align__(16) float pool[8448];

    const int tid = threadIdx.x;      // 0..127
    const int j   = tid;
    const int r0  = blockIdx.x * 2;

    float* table = pool;              // [32][128]
    float* hbuf  = pool + 4096;       // [2][2*128]
    int*   xs    = (int*)(pool + 4608);

    // ---- phase 1 init ----
    for (int c = 0; c < 32; c++) {
        float s = bh[j];
        #pragma unroll 8
        for (int e = 0; e < 32; e++)
            s = fmaf(emb[c * 32 + e], Wxh[e * 128 + j], s);
        table[c * 128 + j] = s;
    }
    hbuf[256 + j] = 0.f; hbuf[256 + 128 + j] = 0.f;   // h_{-1}=0, parity 1

    ULL Wb[64];
    #pragma unroll
    for (int k = 0; k < 64; k++)
        Wb[k] = pack2(Whh[(2 * k) * 128 + j], Whh[(2 * k + 1) * 128 + j]);

    float* scr0 = hsc + (size_t)r0 * 131072;
    float* scr1 = scr0 + 131072;

    // ================= Phase 1: recurrence =================
    for (int t = 0; t < 1024; t++) {
        __syncthreads();                  // h(t-1) visible
        const int tloc = t & 127;
        if (tloc == 0) {
            xs[tid]       = x[r0 * 1024 + t + tid];
            xs[128 + tid] = x[(r0 + 1) * 1024 + t + tid];
            __syncthreads();
        }
        const int br = (t + 1) & 1;
        const int bw = t & 1;

        const ulonglong2* h0 = (const ulonglong2*)(hbuf + br * 256);
        const ulonglong2* h1 = (const ulonglong2*)(hbuf + br * 256 + 128);
        const int c0 = xs[tloc];
        const int c1 = xs[128 + tloc];
        ULL a0 = pack2(table[c0 * 128 + j], 0.0f), a1 = 0ull, a2 = 0ull, a3 = 0ull;
        ULL b0 = pack2(table[c1 * 128 + j], 0.0f), b1 = 0ull, b2 = 0ull, b3 = 0ull;
        #pragma unroll
        for (int k = 0; k < 16; k++) {
            ulonglong2 ha = h0[2 * k];
            ulonglong2 hb = h0[2 * k + 1];
            ulonglong2 hc = h1[2 * k];
            ulonglong2 hd = h1[2 * k + 1];
            a0 = ffma2(ha.x, Wb[4 * k],     a0);
            b0 = ffma2(hc.x, Wb[4 * k],     b0);
            a1 = ffma2(ha.y, Wb[4 * k + 1], a1);
            b1 = ffma2(hc.y, Wb[4 * k + 1], b1);
            a2 = ffma2(hb.x, Wb[4 * k + 2], a2);
            b2 = ffma2(hd.x, Wb[4 * k + 2], b2);
            a3 = ffma2(hb.y, Wb[4 * k + 3], a3);
            b3 = ffma2(hd.y, Wb[4 * k + 3], b3);
        }
        float na = fast_tanh((sum2(a0) + sum2(a1)) + (sum2(a2) + sum2(a3)));
        float nb = fast_tanh((sum2(b0) + sum2(b1)) + (sum2(b2) + sum2(b3)));
        hbuf[bw * 256 + j]       = na;
        hbuf[bw * 256 + 128 + j] = nb;
        scr0[t * 128 + j] = na;
        scr1[t * 128 + j] = nb;
    }

    // final hidden: h(1023) has parity 1
    out[16777216u + (size_t)r0 * 128 + j]       = hbuf[256 + j];
    out[16777216u + (size_t)(r0 + 1) * 128 + j] = hbuf[256 + 128 + j];

    __syncthreads();   // phase-1 smem reads done; hsc writes CTA-visible

    // ================= Phase 2: bulk logits for own rows =================
    float* hs = pool;                         // [32 t][132]
    ULL*   Wp = (ULL*)(pool + 4352);          // [128 i][16 vpair] == (ULL*)Why

    {   // copy W_hy (16 KB) into smem, coalesced
        const float4* wsrc = (const float4*)Why;
        float4* wdst = (float4*)Wp;
        #pragma unroll
        for (int idx = tid; idx < 1024; idx += 128) wdst[idx] = wsrc[idx];
    }
    const int w    = tid >> 5;                // warp: vpairs 4w..4w+3 (v 8w..8w+7)
    const int lane = tid & 31;                // lane: local timestep
    const ULL byA = ((const ULL*)by_g)[4 * w + 0];
    const ULL byB = ((const ULL*)by_g)[4 * w + 1];
    const ULL byC = ((const ULL*)by_g)[4 * w + 2];
    const ULL byD = ((const ULL*)by_g)[4 * w + 3];

    for (int it = 0; it < 64; it++) {
        const int r  = it >> 5;               // row 0/1
        const int t0 = (it & 31) * 32;        // tile start
        __syncthreads();                      // previous tile's reads done
        {   // stage 32x128 h tile (contiguous 16 KB) into padded smem
            const float4* src =
                (const float4*)(hsc + (size_t)(r0 + r) * 131072 + (size_t)t0 * 128);
            #pragma unroll
            for (int idx = tid; idx < 1024; idx += 128) {
                const int tl = idx >> 5;      // 32 float4 per t row
                const int c  = idx & 31;
                *(float4*)(hs + tl * 132 + 4 * c) = src[idx];
            }
        }
        __syncthreads();

        ULL a0 = byA, a1 = byB, a2 = byC, a3 = byD;
        const float* hrow = hs + lane * 132;
        #pragma unroll 8
        for (int gq = 0; gq < 32; gq++) {
            float4 h4 = *(const float4*)(hrow + 4 * gq);
            const ulonglong2* wq =
                (const ulonglong2*)(Wp + (4 * gq) * 16 + 4 * w);
            ulonglong2 w0 = wq[0];   // i = 4gq
            ulonglong2 w1 = wq[8];   // i = 4gq+1   (16 ULL = 8 ulonglong2 per i)
            ulonglong2 w2 = wq[16];  // i = 4gq+2
            ulonglong2 w3 = wq[24];  // i = 4gq+3
            ULL hx = pack2(h4.x, h4.x);
            ULL hy = pack2(h4.y, h4.y);
            ULL hz = pack2(h4.z, h4.z);
            ULL hw = pack2(h4.w, h4.w);
            a0 = ffma2(hx, w0.x, a0);  a1 = ffma2(hx, w0.y, a1);
            a2 = ffma2(hy, w1.x, a2);  a3 = ffma2(hy, w1.y, a3);
            a0 = ffma2(hz, w2.x, a0);  a1 = ffma2(hz, w2.y, a1);
            a2 = ffma2(hw, w3.x, a2);  a3 = ffma2(hw, w3.y, a3);
        }
        // wait: accumulators must stay per-vpair! redo pairing below
        // (a0,a1,a2,a3) hold vpairs (4w..4w+3); each i contributes to ALL 4.
        // The loop above mixed them incorrectly — corrected version:
        (void)0;
        // --- corrected accumulation ---
        a0 = byA; a1 = byB; a2 = byC; a3 = byD;
        #pragma unroll 8
        for (int gq = 0; gq < 32; gq++) {
            float4 h4 = *(const float4*)(hrow + 4 * gq);
            const ulonglong2* wbase =
                (const ulonglong2*)(Wp + (4 * gq) * 16 + 4 * w);
            ULL hx = pack2(h4.x, h4.x);
            ulonglong2 wA0 = wbase[0], wA1 = wbase[1];      // i=4gq,   q pairs
            a0 = ffma2(hx, wA0.x, a0);  a1 = ffma2(hx, wA0.y, a1);
            a2 = ffma2(hx, wA1.x, a2);  a3 = ffma2(hx, wA1.y, a3);
            ULL hy = pack2(h4.y, h4.y);
            ulonglong2 wB0 = wbase[8], wB1 = wbase[9];      // i=4gq+1
            a0 = ffma2(hy, wB0.x, a0);  a1 = ffma2(hy, wB0.y, a1);
            a2 = ffma2(hy, wB1.x, a2);  a3 = ffma2(hy, wB1.y, a3);
            ULL hz = pack2(h4.z, h4.z);
            ulonglong2 wC0 = wbase[16], wC1 = wbase[17];    // i=4gq+2
            a0 = ffma2(hz, wC0.x, a0);  a1 = ffma2(hz, wC0.y, a1);
            a2 = ffma2(hz, wC1.x, a2);  a3 = ffma2(hz, wC1.y, a3);
            ULL hw = pack2(h4.w, h4.w);
            ulonglong2 wD0 = wbase[24], wD1 = wbase[25];    // i=4gq+3
            a0 = ffma2(hw, wD0.x, a0);  a1 = ffma2(hw, wD0.y, a1);
            a2 = ffma2(hw, wD1.x, a2);  a3 = ffma2(hw, wD1.y, a3);
        }
        float* dst = out + ((size_t)(r0 + r) * 1024 + t0 + lane) * 32 + 8 * w;
        ulonglong2 s01; s01.x = a0; s01.y = a1;
        ulonglong2 s23; s23.x = a2; s23.y = a3;
        *(ulonglong2*)(dst)     = s01;
        *(ulonglong2*)(dst + 4) = s23;
    }
}

extern "C" void kernel_launch(void* const* d_in, const int* in_sizes, int n_in,
                              void* d_out, int out_size) {
    (void)in_sizes; (void)n_in; (void)out_size;
    const int*   x   = (const int*)d_in[0];
    const float* emb = (const float*)d_in[1];
    const float* Wxh = (const float*)d_in[2];
    const float* Whh = (const float*)d_in[3];
    const float* bh  = (const float*)d_in[4];
    const float* Why = (const float*)d_in[5];
    const float* by  = (const float*)d_in[6];
    float* out = (float*)d_out;

    charrnn_kernel<<<256, 128>>>(x, emb, Wxh, Whh, bh, Why, by, out);
}

// round 15
// speedup vs baseline: 1.7383x; 1.0712x over previous
#include <cuda_runtime.h>
#include <math.h>

// CharRNN, round 13: col-pair + i-half decomposition to halve LDS traffic.
// Phase 1: 256 CTAs x 128 thr, 2 rows/CTA, 2 CTAs/SM. Thread (q=tid&1,
//   jj=tid>>1) holds W_hh[i][c] for i in [64q,64q+64), c in {jj, jj+64}
//   (64 f32x2 regs). h stored block-swizzled so paired loads are 1 wf.
//   Partials combined via shfl.bfly(1); thread q owns row q's outputs.
//   One __syncthreads/step; h(t) streamed (swizzled) to global scratch.
// Phase 2: bulk logits from scratch (W_hy in smem, h staged+unswizzled).

#define ULL unsigned long long

__device__ float hsc[67108864];   // [512 rows][1024 t][128] (block-swizzled)

__device__ __forceinline__ ULL ffma2(ULL a, ULL b, ULL c) {
    ULL d;
    asm("fma.rn.f32x2 %0, %1, %2, %3;" : "=l"(d) : "l"(a), "l"(b), "l"(c));
    return d;
}
__device__ __forceinline__ ULL addf2(ULL a, ULL b) {
    ULL d;
    asm("add.rn.f32x2 %0, %1, %2;" : "=l"(d) : "l"(a), "l"(b));
    return d;
}
__device__ __forceinline__ ULL pack2(float lo, float hi) {
    ULL d;
    asm("mov.b64 %0, {%1, %2};" : "=l"(d) : "f"(lo), "f"(hi));
    return d;
}
__device__ __forceinline__ float sum2(ULL a) {
    float lo, hi;
    asm("mov.b64 {%0, %1}, %2;" : "=f"(lo), "=f"(hi) : "l"(a));
    return lo + hi;
}
__device__ __forceinline__ float fast_tanh(float x) {
    return 1.0f - __fdividef(2.0f, __expf(2.0f * x) + 1.0f);
}

// Swizzle: h[64Q + 4M + E]  lives at float offset  M*8 + Q*4 + E  (per row).

// pool (floats): phase1: table[0,4096) | hbuf[4096,4608) | xs(int)[4608,4864)
//                phase2: hs[0,4224) | Wp ULL[2048] at [4352,8448)
__global__ void __launch_bounds__(128, 2) charrnn_kernel(
    const int*   __restrict__ x,      // [512][1024]
    const float* __restrict__ emb,    // [32][32]
    const float* __restrict__ Wxh,    // [32][128]
    const float* __restrict__ Whh,    // [128][128]
    const float* __restrict__ bh,     // [128]
    const float* __restrict__ Why,    // [128][32]
    const float* __restrict__ by_g,   // [32]
    float*       __restrict__ out)    // logits [512][1024][32] ++ hidden [512][128]
{
    __shared__ __align__(16) float pool[8448];

    const int tid = threadIdx.x;      // 0..127
    const int q   = tid & 1;          // i-half (and owned row)
    const int jj  = tid >> 1;         // first column; second is jj+64
    const int r0  = blockIdx.x * 2;

    float* table = pool;              // [32][128] standard layout
    float* hbuf  = pool + 4096;       // [2][2*128] swizzled per row
    int*   xs    = (int*)(pool + 4608);

    // ---- init: xh table (standard layout, thread=column tid) ----
    for (int c = 0; c < 32; c++) {
        float s = bh[tid];
        #pragma unroll 8
        for (int e = 0; e < 32; e++)
            s = fmaf(emb[c * 32 + e], Wxh[e * 128 + tid], s);
        table[c * 128 + tid] = s;
    }
    hbuf[256 + tid] = 0.f; hbuf[384 + tid] = 0.f;   // h_{-1}=0, parity 1

    // W_hh: i-half [64q,64q+64) for columns jj and jj+64, i-pair packed
    ULL W0[32], W1[32];
    #pragma unroll
    for (int k = 0; k < 32; k++) {
        const int i0 = 64 * q + 2 * k;
        W0[k] = pack2(Whh[i0 * 128 + jj],      Whh[(i0 + 1) * 128 + jj]);
        W1[k] = pack2(Whh[i0 * 128 + jj + 64], Whh[(i0 + 1) * 128 + jj + 64]);
    }

    const int off0 = ((jj >> 2) << 3) + (jj & 3);  // swizzled slot of col jj
    const int off1 = off0 + 4;                     // swizzled slot of col jj+64
    float* scrq = hsc + (size_t)(r0 + q) * 131072; // own row's history

    // anti-phase the two co-resident CTAs
    if (blockIdx.x & 1) {
        long long s0 = clock64();
        while (clock64() - s0 < 800) { }
    }

    // ================= Phase 1: recurrence =================
    for (int t = 0; t < 1024; t++) {
        __syncthreads();                  // h(t-1) visible
        const int tloc = t & 127;
        if (tloc == 0) {
            xs[tid]       = x[r0 * 1024 + t + tid];
            xs[128 + tid] = x[(r0 + 1) * 1024 + t + tid];
            __syncthreads();
        }
        const int br = (t + 1) & 1;
        const int bw = t & 1;

        const float* h0 = hbuf + br * 256 + q * 4;        // row 0, my half's blocks
        const float* h1 = h0 + 128;                       // row 1
        // 8 chains, 16 deep: rows {a,b} x cols {0,1} x parity {x,y}
        ULL aA = 0ull, aB = 0ull, aC = 0ull, aD = 0ull;
        ULL bA = 0ull, bB = 0ull, bC = 0ull, bD = 0ull;
        #pragma unroll
        for (int m = 0; m < 16; m++) {
            ulonglong2 u0 = *(const ulonglong2*)(h0 + m * 8);
            ulonglong2 u1 = *(const ulonglong2*)(h1 + m * 8);
            aA = ffma2(u0.x, W0[2 * m],     aA);
            bA = ffma2(u1.x, W0[2 * m],     bA);
            aB = ffma2(u0.y, W0[2 * m + 1], aB);
            bB = ffma2(u1.y, W0[2 * m + 1], bB);
            aC = ffma2(u0.x, W1[2 * m],     aC);
            bC = ffma2(u1.x, W1[2 * m],     bC);
            aD = ffma2(u0.y, W1[2 * m + 1], aD);
            bD = ffma2(u1.y, W1[2 * m + 1], bD);
        }
        float f00 = sum2(addf2(aA, aB));   // row0, col jj     (half-partial)
        float f01 = sum2(addf2(aC, aD));   // row0, col jj+64
        float f10 = sum2(addf2(bA, bB));   // row1, col jj
        float f11 = sum2(addf2(bC, bD));   // row1, col jj+64
        // combine i-halves with adjacent lane
        f00 += __shfl_xor_sync(0xffffffffu, f00, 1);
        f01 += __shfl_xor_sync(0xffffffffu, f01, 1);
        f10 += __shfl_xor_sync(0xffffffffu, f10, 1);
        f11 += __shfl_xor_sync(0xffffffffu, f11, 1);
        // thread q owns row q
        const int tok = xs[q * 128 + tloc];
        float v0 = (q ? f10 : f00) + table[tok * 128 + jj];
        float v1 = (q ? f11 : f01) + table[tok * 128 + jj + 64];
        v0 = fast_tanh(v0);
        v1 = fast_tanh(v1);
        float* hw = hbuf + bw * 256 + q * 128;
        hw[off0] = v0;
        hw[off1] = v1;
        float* sc = scrq + t * 128;       // swizzled history
        sc[off0] = v0;
        sc[off1] = v1;
    }

    // ---- final hidden (un-swizzle): out wants standard h[j] ----
    {
        const int Q = tid >> 6, M = (tid & 63) >> 2, E = tid & 3;
        const int offj = M * 8 + Q * 4 + E;
        out[16777216u + (size_t)r0 * 128 + tid]       = hbuf[256 + offj];
        out[16777216u + (size_t)(r0 + 1) * 128 + tid] = hbuf[256 + 128 + offj];
    }

    __syncthreads();   // phase-1 smem reads done; hsc writes CTA-visible

    // ================= Phase 2: bulk logits for own rows =================
    float* hs = pool;                         // [32 t][132] (un-swizzled)
    ULL*   Wp = (ULL*)(pool + 4352);          // == (ULL*)Why

    {   // copy W_hy (16 KB) into smem, coalesced
        const float4* wsrc = (const float4*)Why;
        float4* wdst = (float4*)Wp;
        #pragma unroll
        for (int idx = tid; idx < 1024; idx += 128) wdst[idx] = wsrc[idx];
    }
    const int w    = tid >> 5;                // warp: v-pairs 4w..4w+3
    const int lane = tid & 31;                // lane: local timestep
    const ULL byA = ((const ULL*)by_g)[4 * w + 0];
    const ULL byB = ((const ULL*)by_g)[4 * w + 1];
    const ULL byC = ((const ULL*)by_g)[4 * w + 2];
    const ULL byD = ((const ULL*)by_g)[4 * w + 3];

    for (int it = 0; it < 64; it++) {
        const int r  = it >> 5;               // row 0/1
        const int t0 = (it & 31) * 32;        // tile start
        __syncthreads();                      // previous tile's reads done
        {   // stage 32x128 h tile, un-swizzling block b -> i = 64(b&1)+4(b>>1)
            const float4* src =
                (const float4*)(hsc + (size_t)(r0 + r) * 131072 + (size_t)t0 * 128);
            #pragma unroll
            for (int idx = tid; idx < 1024; idx += 128) {
                const int tl  = idx >> 5;
                const int blk = idx & 31;
                const int dst = 64 * (blk & 1) + 4 * (blk >> 1);
                *(float4*)(hs + tl * 132 + dst) = src[idx];
            }
        }
        __syncthreads();

        const float* hrow = hs + lane * 132;
        ULL a0 = byA, a1 = byB, a2 = byC, a3 = byD;
        #pragma unroll 8
        for (int gq = 0; gq < 32; gq++) {
            float4 h4 = *(const float4*)(hrow + 4 * gq);
            const ulonglong2* wbase =
                (const ulonglong2*)(Wp + (4 * gq) * 16 + 4 * w);
            ULL hx = pack2(h4.x, h4.x);
            ulonglong2 wA0 = wbase[0], wA1 = wbase[1];      // i=4gq
            a0 = ffma2(hx, wA0.x, a0);  a1 = ffma2(hx, wA0.y, a1);
            a2 = ffma2(hx, wA1.x, a2);  a3 = ffma2(hx, wA1.y, a3);
            ULL hy = pack2(h4.y, h4.y);
            ulonglong2 wB0 = wbase[8], wB1 = wbase[9];      // i=4gq+1
            a0 = ffma2(hy, wB0.x, a0);  a1 = ffma2(hy, wB0.y, a1);
            a2 = ffma2(hy, wB1.x, a2);  a3 = ffma2(hy, wB1.y, a3);
            ULL hz = pack2(h4.z, h4.z);
            ulonglong2 wC0 = wbase[16], wC1 = wbase[17];    // i=4gq+2
            a0 = ffma2(hz, wC0.x, a0);  a1 = ffma2(hz, wC0.y, a1);
            a2 = ffma2(hz, wC1.x, a2);  a3 = ffma2(hz, wC1.y, a3);
            ULL hw4 = pack2(h4.w, h4.w);
            ulonglong2 wD0 = wbase[24], wD1 = wbase[25];    // i=4gq+3
            a0 = ffma2(hw4, wD0.x, a0); a1 = ffma2(hw4, wD0.y, a1);
            a2 = ffma2(hw4, wD1.x, a2); a3 = ffma2(hw4, wD1.y, a3);
        }
        float* dst = out + ((size_t)(r0 + r) * 1024 + t0 + lane) * 32 + 8 * w;
        ulonglong2 s01; s01.x = a0; s01.y = a1;
        ulonglong2 s23; s23.x = a2; s23.y = a3;
        *(ulonglong2*)(dst)     = s01;
        *(ulonglong2*)(dst + 4) = s23;
    }
}

extern "C" void kernel_launch(void* const* d_in, const int* in_sizes, int n_in,
                              void* d_out, int out_size) {
    (void)in_sizes; (void)n_in; (void)out_size;
    const int*   x   = (const int*)d_in[0];
    const float* emb = (const float*)d_in[1];
    const float* Wxh = (const float*)d_in[2];
    const float* Whh = (const float*)d_in[3];
    const float* bh  = (const float*)d_in[4];
    const float* Why = (const float*)d_in[5];
    const float* by  = (const float*)d_in[6];
    float* out = (float*)d_out;

    charrnn_kernel<<<256, 128>>>(x, emb, Wxh, Whh, bh, Why, by, out);
}

// round 16
// speedup vs baseline: 1.8254x; 1.0501x over previous
#include <cuda_runtime.h>
#include <math.h>

// CharRNN, round 16: R13 layout + tail cuts.
// Phase 1: 256 CTAs x 128 thr, 2 rows/CTA, 2 CTAs/SM. Thread (q=tid&1,
//   jj=tid>>1) holds W_hh[i][c] for i in [64q,64q+64), c in {jj, jj+64}.
//   h block-swizzled in smem; 2-shuffle cross-row combine; MUFU tanh.approx;
//   tokens fully preloaded (no mid-loop refill barriers).
// Phase 2: bulk logits from scratch (unchanged from R13).

#define ULL unsigned long long

__device__ float hsc[67108864];   // [512 rows][1024 t][128] (block-swizzled)

__device__ __forceinline__ ULL ffma2(ULL a, ULL b, ULL c) {
    ULL d;
    asm("fma.rn.f32x2 %0, %1, %2, %3;" : "=l"(d) : "l"(a), "l"(b), "l"(c));
    return d;
}
__device__ __forceinline__ ULL addf2(ULL a, ULL b) {
    ULL d;
    asm("add.rn.f32x2 %0, %1, %2;" : "=l"(d) : "l"(a), "l"(b));
    return d;
}
__device__ __forceinline__ ULL pack2(float lo, float hi) {
    ULL d;
    asm("mov.b64 %0, {%1, %2};" : "=l"(d) : "f"(lo), "f"(hi));
    return d;
}
__device__ __forceinline__ float sum2(ULL a) {
    float lo, hi;
    asm("mov.b64 {%0, %1}, %2;" : "=f"(lo), "=f"(hi) : "l"(a));
    return lo + hi;
}
__device__ __forceinline__ float tanh_a(float x) {
    float y;
    asm("tanh.approx.f32 %0, %1;" : "=f"(y) : "f"(x));
    return y;
}

// Swizzle: h[64Q + 4M + E] lives at float offset M*8 + Q*4 + E (per row).
// pool (floats): phase1: table[0,4096) | hbuf[4096,4608) | xs(int)[4608,6656)
//                phase2: hs[0,4224) | Wp ULL[2048] at [4352,8448)
__global__ void __launch_bounds__(128, 2) charrnn_kernel(
    const int*   __restrict__ x,      // [512][1024]
    const float* __restrict__ emb,    // [32][32]
    const float* __restrict__ Wxh,    // [32][128]
    const float* __restrict__ Whh,    // [128][128]
    const float* __restrict__ bh,     // [128]
    const float* __restrict__ Why,    // [128][32]
    const float* __restrict__ by_g,   // [32]
    float*       __restrict__ out)    // logits [512][1024][32] ++ hidden [512][128]
{
    __shared__ __align__(16) float pool[8448];

    const int tid = threadIdx.x;      // 0..127
    const int q   = tid & 1;          // i-half (and owned row)
    const int jj  = tid >> 1;         // first column; second is jj+64
    const int r0  = blockIdx.x * 2;

    float* table = pool;              // [32][128] standard layout
    float* hbuf  = pool + 4096;       // [2][2*128] swizzled per row
    int*   xsf   = (int*)(pool + 4608);   // [2][1024] full token streams

    // ---- init ----
    for (int c = 0; c < 32; c++) {
        float s = bh[tid];
        #pragma unroll 8
        for (int e = 0; e < 32; e++)
            s = fmaf(emb[c * 32 + e], Wxh[e * 128 + tid], s);
        table[c * 128 + tid] = s;
    }
    #pragma unroll
    for (int idx = tid; idx < 2048; idx += 128)
        xsf[idx] = x[r0 * 1024 + idx];          // rows r0, r0+1 contiguous
    hbuf[256 + tid] = 0.f; hbuf[384 + tid] = 0.f;   // h_{-1}=0, parity 1

    ULL W0[32], W1[32];
    #pragma unroll
    for (int k = 0; k < 32; k++) {
        const int i0 = 64 * q + 2 * k;
        W0[k] = pack2(Whh[i0 * 128 + jj],      Whh[(i0 + 1) * 128 + jj]);
        W1[k] = pack2(Whh[i0 * 128 + jj + 64], Whh[(i0 + 1) * 128 + jj + 64]);
    }

    const int off0 = ((jj >> 2) << 3) + (jj & 3);  // swizzled slot of col jj
    const int off1 = off0 + 4;                     // swizzled slot of col jj+64
    float* scrq = hsc + (size_t)(r0 + q) * 131072; // own row's history
    const int* xq = xsf + q * 1024;                // own row's tokens

    // anti-phase the two co-resident CTAs
    if (blockIdx.x & 1) {
        long long s0 = clock64();
        while (clock64() - s0 < 800) { }
    }

    // ================= Phase 1: recurrence =================
    for (int t = 0; t < 1024; t++) {
        __syncthreads();                  // h(t-1) visible
        const int br = (t + 1) & 1;
        const int bw = t & 1;

        // early: token + xh table values (off the post-shuffle path)
        const int tok = xq[t];
        const float tb0 = table[tok * 128 + jj];
        const float tb1 = table[tok * 128 + jj + 64];

        const float* h0 = hbuf + br * 256 + q * 4;        // row 0, my half
        const float* h1 = h0 + 128;                       // row 1
        ULL aA = 0ull, aB = 0ull, aC = 0ull, aD = 0ull;   // row 0
        ULL bA = 0ull, bB = 0ull, bC = 0ull, bD = 0ull;   // row 1
        #pragma unroll
        for (int m = 0; m < 16; m++) {
            ulonglong2 u0 = *(const ulonglong2*)(h0 + m * 8);
            ulonglong2 u1 = *(const ulonglong2*)(h1 + m * 8);
            aA = ffma2(u0.x, W0[2 * m],     aA);
            bA = ffma2(u1.x, W0[2 * m],     bA);
            aB = ffma2(u0.y, W0[2 * m + 1], aB);
            bB = ffma2(u1.y, W0[2 * m + 1], bB);
            aC = ffma2(u0.x, W1[2 * m],     aC);
            bC = ffma2(u1.x, W1[2 * m],     bC);
            aD = ffma2(u0.y, W1[2 * m + 1], aD);
            bD = ffma2(u1.y, W1[2 * m + 1], bD);
        }
        // other-row (1-q) partials first: q==0 -> row1 (b), q==1 -> row0 (a)
        float so0 = sum2(addf2(q ? aA : bA, q ? aB : bB));   // other row, col jj
        float so1 = sum2(addf2(q ? aC : bC, q ? aD : bD));   // other row, col jj+64
        float rv0 = __shfl_xor_sync(0xffffffffu, so0, 1);    // partner's own-row partial
        float rv1 = __shfl_xor_sync(0xffffffffu, so1, 1);
        // own-row (q) sums overlap the shuffle latency
        float f0 = sum2(addf2(q ? bA : aA, q ? bB : aB)) + tb0;
        float f1 = sum2(addf2(q ? bC : aC, q ? bD : aD)) + tb1;
        float v0 = tanh_a(f0 + rv0);
        float v1 = tanh_a(f1 + rv1);

        float* hw = hbuf + bw * 256 + q * 128;
        hw[off0] = v0;
        hw[off1] = v1;
        float* sc = scrq + t * 128;       // swizzled history stream
        sc[off0] = v0;
        sc[off1] = v1;
    }

    // ---- final hidden (un-swizzle) ----
    {
        const int Q = tid >> 6, M = (tid & 63) >> 2, E = tid & 3;
        const int offj = M * 8 + Q * 4 + E;
        out[16777216u + (size_t)r0 * 128 + tid]       = hbuf[256 + offj];
        out[16777216u + (size_t)(r0 + 1) * 128 + tid] = hbuf[256 + 128 + offj];
    }

    __syncthreads();   // phase-1 smem reads done; hsc writes CTA-visible

    // ================= Phase 2: bulk logits for own rows =================
    float* hs = pool;                         // [32 t][132] (un-swizzled)
    ULL*   Wp = (ULL*)(pool + 4352);          // == (ULL*)Why

    {
        const float4* wsrc = (const float4*)Why;
        float4* wdst = (float4*)Wp;
        #pragma unroll
        for (int idx = tid; idx < 1024; idx += 128) wdst[idx] = wsrc[idx];
    }
    const int w    = tid >> 5;                // warp: v-pairs 4w..4w+3
    const int lane = tid & 31;                // lane: local timestep
    const ULL byA = ((const ULL*)by_g)[4 * w + 0];
    const ULL byB = ((const ULL*)by_g)[4 * w + 1];
    const ULL byC = ((const ULL*)by_g)[4 * w + 2];
    const ULL byD = ((const ULL*)by_g)[4 * w + 3];

    for (int it = 0; it < 64; it++) {
        const int r  = it >> 5;               // row 0/1
        const int t0 = (it & 31) * 32;        // tile start
        __syncthreads();                      // previous tile's reads done
        {   // stage 32x128 h tile, un-swizzling block b -> i = 64(b&1)+4(b>>1)
            const float4* src =
                (const float4*)(hsc + (size_t)(r0 + r) * 131072 + (size_t)t0 * 128);
            #pragma unroll
            for (int idx = tid; idx < 1024; idx += 128) {
                const int tl  = idx >> 5;
                const int blk = idx & 31;
                const int dst = 64 * (blk & 1) + 4 * (blk >> 1);
                *(float4*)(hs + tl * 132 + dst) = src[idx];
            }
        }
        __syncthreads();

        const float* hrow = hs + lane * 132;
        ULL a0 = byA, a1 = byB, a2 = byC, a3 = byD;
        #pragma unroll 8
        for (int gq = 0; gq < 32; gq++) {
            float4 h4 = *(const float4*)(hrow + 4 * gq);
            const ulonglong2* wbase =
                (const ulonglong2*)(Wp + (4 * gq) * 16 + 4 * w);
            ULL hx = pack2(h4.x, h4.x);
            ulonglong2 wA0 = wbase[0], wA1 = wbase[1];      // i=4gq
            a0 = ffma2(hx, wA0.x, a0);  a1 = ffma2(hx, wA0.y, a1);
            a2 = ffma2(hx, wA1.x, a2);  a3 = ffma2(hx, wA1.y, a3);
            ULL hy = pack2(h4.y, h4.y);
            ulonglong2 wB0 = wbase[8], wB1 = wbase[9];      // i=4gq+1
            a0 = ffma2(hy, wB0.x, a0);  a1 = ffma2(hy, wB0.y, a1);
            a2 = ffma2(hy, wB1.x, a2);  a3 = ffma2(hy, wB1.y, a3);
            ULL hz = pack2(h4.z, h4.z);
            ulonglong2 wC0 = wbase[16], wC1 = wbase[17];    // i=4gq+2
            a0 = ffma2(hz, wC0.x, a0);  a1 = ffma2(hz, wC0.y, a1);
            a2 = ffma2(hz, wC1.x, a2);  a3 = ffma2(hz, wC1.y, a3);
            ULL hw4 = pack2(h4.w, h4.w);
            ulonglong2 wD0 = wbase[24], wD1 = wbase[25];    // i=4gq+3
            a0 = ffma2(hw4, wD0.x, a0); a1 = ffma2(hw4, wD0.y, a1);
            a2 = ffma2(hw4, wD1.x, a2); a3 = ffma2(hw4, wD1.y, a3);
        }
        float* dst = out + ((size_t)(r0 + r) * 1024 + t0 + lane) * 32 + 8 * w;
        ulonglong2 s01; s01.x = a0; s01.y = a1;
        ulonglong2 s23; s23.x = a2; s23.y = a3;
        *(ulonglong2*)(dst)     = s01;
        *(ulonglong2*)(dst + 4) = s23;
    }
}

extern "C" void kernel_launch(void* const* d_in, const int* in_sizes, int n_in,
                              void* d_out, int out_size) {
    (void)in_sizes; (void)n_in; (void)out_size;
    const int*   x   = (const int*)d_in[0];
    const float* emb = (const float*)d_in[1];
    const float* Wxh = (const float*)d_in[2];
    const float* Whh = (const float*)d_in[3];
    const float* bh  = (const float*)d_in[4];
    const float* Why = (const float*)d_in[5];
    const float* by  = (const float*)d_in[6];
    float* out = (float*)d_out;

    charrnn_kernel<<<256, 128>>>(x, emb, Wxh, Whh, bh, Why, by, out);
}